// round 5
// baseline (speedup 1.0000x reference)
#include <cuda_runtime.h>
#include <cuda_bf16.h>

#define H     128
#define NSEG  512
#define RANKS 3
#define LN_EPS 1e-5f
#define U     8      // rows per group in agg kernel
#define SEGT  8      // segments per block in proj kernel
#define HSEG  4      // segments per block in head kernel

// ---------------- scratch (no allocations allowed) ----------------
__device__ float g_sum [RANKS * NSEG * H];
__device__ float g_gsum[RANKS * NSEG * H];
__device__ float g_max [RANKS * NSEG * H];
__device__ float g_cnt [RANKS * NSEG];
__device__ float g_r   [RANKS * NSEG * H];

// ---------------- helpers ----------------
__device__ __forceinline__ void atomicMaxF(float* addr, float v) {
    if (v >= 0.f) atomicMax((int*)addr, __float_as_int(v));
    else          atomicMin((unsigned int*)addr, __float_as_uint(v));
}

__device__ __forceinline__ float warp_sum(float v) {
    v += __shfl_xor_sync(0xffffffffu, v, 16);
    v += __shfl_xor_sync(0xffffffffu, v, 8);
    v += __shfl_xor_sync(0xffffffffu, v, 4);
    v += __shfl_xor_sync(0xffffffffu, v, 2);
    v += __shfl_xor_sync(0xffffffffu, v, 1);
    return v;
}

__device__ __forceinline__ float silu(float x) {
    return x / (1.f + __expf(-x));
}

// ---------------- 1. zero accumulators ----------------
__global__ void zero_kernel() {
    int i = blockIdx.x * blockDim.x + threadIdx.x;
    if (i < RANKS * NSEG * H) {
        g_sum[i]  = 0.f;
        g_gsum[i] = 0.f;
        g_max[i]  = __int_as_float(0xff800000);  // -inf
    }
    if (i < RANKS * NSEG) g_cnt[i] = 0.f;
}

// ---------------- 2. single-pass gated multi-aggregation ----------------
// Warp-per-contiguous-chunk; 8-row groups for MLP=8 and interleaved butterflies.
__global__ __launch_bounds__(256) void agg_kernel(
    const float* __restrict__ h0, const float* __restrict__ h1, const float* __restrict__ h2,
    const int*   __restrict__ b0, const int*   __restrict__ b1, const int*   __restrict__ b2,
    const float* __restrict__ Wg0, const float* __restrict__ Wg1, const float* __restrict__ Wg2,
    const float* __restrict__ bg0, const float* __restrict__ bg1, const float* __restrict__ bg2,
    int N0, int N1, int N2)
{
    const int rank = blockIdx.y;
    const float* h;  const int* b;  const float* Wg;  float bg;  int N;
    if (rank == 0)      { h = h0; b = b0; Wg = Wg0; bg = bg0[0]; N = N0; }
    else if (rank == 1) { h = h1; b = b1; Wg = Wg1; bg = bg1[0]; N = N1; }
    else                { h = h2; b = b2; Wg = Wg2; bg = bg2[0]; N = N2; }

    const int lane          = threadIdx.x & 31;
    const int warpsPerBlock = blockDim.x >> 5;
    const int gw            = blockIdx.x * warpsPerBlock + (threadIdx.x >> 5);
    const int totalWarps    = gridDim.x * warpsPerBlock;
    const int chunk         = (N + totalWarps - 1) / totalWarps;
    const int start         = gw * chunk;
    const int end           = min(start + chunk, N);
    if (start >= end) return;

    const float4 wg  = reinterpret_cast<const float4*>(Wg)[lane];
    const float  NEG = __int_as_float(0xff800000);

    float4 s  = make_float4(0.f, 0.f, 0.f, 0.f);
    float4 gs = make_float4(0.f, 0.f, 0.f, 0.f);
    float4 mx = make_float4(NEG, NEG, NEG, NEG);
    float  cnt = 0.f;
    int    cur = __ldg(&b[start]);

    #define FLUSH()                                                          \
    do {                                                                     \
        const int _base = (rank * NSEG + cur) * H + lane * 4;                \
        atomicAdd(&g_sum [_base + 0], s.x);  atomicAdd(&g_sum [_base + 1], s.y);  \
        atomicAdd(&g_sum [_base + 2], s.z);  atomicAdd(&g_sum [_base + 3], s.w);  \
        atomicAdd(&g_gsum[_base + 0], gs.x); atomicAdd(&g_gsum[_base + 1], gs.y); \
        atomicAdd(&g_gsum[_base + 2], gs.z); atomicAdd(&g_gsum[_base + 3], gs.w); \
        atomicMaxF(&g_max[_base + 0], mx.x); atomicMaxF(&g_max[_base + 1], mx.y); \
        atomicMaxF(&g_max[_base + 2], mx.z); atomicMaxF(&g_max[_base + 3], mx.w); \
        if (lane == 0) atomicAdd(&g_cnt[rank * NSEG + cur], cnt);            \
        s  = make_float4(0.f, 0.f, 0.f, 0.f);                                \
        gs = make_float4(0.f, 0.f, 0.f, 0.f);                                \
        mx = make_float4(NEG, NEG, NEG, NEG);                                \
        cnt = 0.f;                                                           \
    } while (0)

    int row = start;

    for (; row + U <= end; row += U) {
        float4 hv[U];
        int    sg[U];
        float  p[U];
        #pragma unroll
        for (int i = 0; i < U; ++i) {
            hv[i] = reinterpret_cast<const float4*>(h + (size_t)(row + i) * H)[lane];
            sg[i] = __ldg(&b[row + i]);
        }
        #pragma unroll
        for (int i = 0; i < U; ++i)
            p[i] = hv[i].x * wg.x + hv[i].y * wg.y + hv[i].z * wg.z + hv[i].w * wg.w;

        #pragma unroll
        for (int off = 16; off; off >>= 1) {
            #pragma unroll
            for (int i = 0; i < U; ++i)
                p[i] += __shfl_xor_sync(0xffffffffu, p[i], off);
        }

        #pragma unroll
        for (int i = 0; i < U; ++i) {
            if (sg[i] != cur) { FLUSH(); cur = sg[i]; }
            const float g = 1.f / (1.f + __expf(-(p[i] + bg)));
            s.x += hv[i].x; s.y += hv[i].y; s.z += hv[i].z; s.w += hv[i].w;
            gs.x = fmaf(g, hv[i].x, gs.x); gs.y = fmaf(g, hv[i].y, gs.y);
            gs.z = fmaf(g, hv[i].z, gs.z); gs.w = fmaf(g, hv[i].w, gs.w);
            mx.x = fmaxf(mx.x, hv[i].x);  mx.y = fmaxf(mx.y, hv[i].y);
            mx.z = fmaxf(mx.z, hv[i].z);  mx.w = fmaxf(mx.w, hv[i].w);
            cnt += 1.f;
        }
    }

    for (; row < end; ++row) {
        float4 hv = reinterpret_cast<const float4*>(h + (size_t)row * H)[lane];
        int    sg = __ldg(&b[row]);
        if (sg != cur) { FLUSH(); cur = sg; }
        float p = hv.x * wg.x + hv.y * wg.y + hv.z * wg.z + hv.w * wg.w;
        p = warp_sum(p);
        const float g = 1.f / (1.f + __expf(-(p + bg)));
        s.x += hv.x; s.y += hv.y; s.z += hv.z; s.w += hv.w;
        gs.x = fmaf(g, hv.x, gs.x); gs.y = fmaf(g, hv.y, gs.y);
        gs.z = fmaf(g, hv.z, gs.z); gs.w = fmaf(g, hv.w, gs.w);
        mx.x = fmaxf(mx.x, hv.x);  mx.y = fmaxf(mx.y, hv.y);
        mx.z = fmaxf(mx.z, hv.z);  mx.w = fmaxf(mx.w, hv.w);
        cnt += 1.f;
    }

    FLUSH();
    #undef FLUSH
}

// ---------------- 3. per-rank projection: agg[B,4H] @ Wp[4H,H] + bp ----------------
// Seg-tiled: 8 segments per block -> Wp columns read once per 8 segments.
// 512 threads: j = t&127, sgrp = t>>7 handles 2 local segments.
__global__ __launch_bounds__(512) void proj_kernel(
    const float* __restrict__ Wp0, const float* __restrict__ bp0,
    const float* __restrict__ Wp1, const float* __restrict__ bp1,
    const float* __restrict__ Wp2, const float* __restrict__ bp2)
{
    const int rank    = blockIdx.y;
    const int segBase = blockIdx.x * SEGT;
    const int t       = threadIdx.x;

    const float* Wp = (rank == 0) ? Wp0 : (rank == 1) ? Wp1 : Wp2;
    const float* bp = (rank == 0) ? bp0 : (rank == 1) ? bp1 : bp2;

    // transposed agg staging: saggT[k][sl], k in [0,512), sl in [0,SEGT)
    __shared__ __align__(16) float saggT[4 * H * SEGT];

    for (int idx = t; idx < SEGT * 4 * H; idx += 512) {
        const int sl  = idx >> 9;        // idx / 512
        const int k   = idx & 511;
        const int seg = segBase + sl;
        const int gb  = (rank * NSEG + seg) * H;
        const float cnt = g_cnt[rank * NSEG + seg];
        const int q  = k >> 7;
        const int jj = k & 127;
        float val;
        if (q == 0)      val = g_sum[gb + jj];
        else if (q == 1) val = g_sum[gb + jj] / fmaxf(cnt, 1.f);
        else if (q == 2) { const float mv = g_max[gb + jj]; val = (cnt > 0.f) ? mv : 0.f; }
        else             val = g_gsum[gb + jj];
        saggT[k * SEGT + sl] = val;
    }
    __syncthreads();

    const int j    = t & (H - 1);
    const int sgrp = t >> 7;          // 0..3
    const int s0   = sgrp * 2;        // local segs s0, s0+1

    float a0 = 0.f, a1 = 0.f;
    #pragma unroll 8
    for (int k = 0; k < 4 * H; ++k) {
        const float  w  = Wp[k * H + j];
        const float2 sv = *reinterpret_cast<const float2*>(&saggT[k * SEGT + s0]);
        a0 = fmaf(sv.x, w, a0);
        a1 = fmaf(sv.y, w, a1);
    }

    const float bj = bp[j];
    const int gb = (rank * NSEG + segBase + s0) * H + j;
    g_r[gb]     = a0 + bj;
    g_r[gb + H] = a1 + bj;
}

// ---------------- 4. head: concat -> LayerNorm -> SiLU -> W1 -> SiLU -> W2 ----------------
// 4 segments per block; W1 read once per 4 segments; k split across 2 halves.
__global__ __launch_bounds__(256) void head_kernel(
    const float* __restrict__ gamma, const float* __restrict__ beta,
    const float* __restrict__ W1,    const float* __restrict__ b1f,
    const float* __restrict__ W2,    const float* __restrict__ b2f,
    float* __restrict__ out)
{
    const int t    = threadIdx.x;
    const int j    = t & (H - 1);
    const int sub  = t >> 7;          // 0 or 1
    const int warp = t >> 5;          // 0..7

    __shared__ __align__(16) float sxT[3 * H * HSEG];   // [k][seg]
    __shared__ float  red[8];
    __shared__ float4 part[2][H];
    __shared__ float  o_red[4][HSEG];

    const float gma0 = gamma[j], gma1 = gamma[H + j], gma2 = gamma[2 * H + j];
    const float bta0 = beta[j],  bta1 = beta[H + j],  bta2 = beta[2 * H + j];

    // ---- LayerNorm + SiLU for 2 segs per half (4 total) ----
    for (int it = 0; it < 2; ++it) {
        const int sl  = sub * 2 + it;
        const int seg = blockIdx.x * HSEG + sl;

        const float v0 = g_r[(0 * NSEG + seg) * H + j];
        const float v1 = g_r[(1 * NSEG + seg) * H + j];
        const float v2 = g_r[(2 * NSEG + seg) * H + j];

        float loc = warp_sum(v0 + v1 + v2);
        if ((t & 31) == 0) red[warp] = loc;
        __syncthreads();
        const float mu = ((sub == 0) ? (red[0] + red[1] + red[2] + red[3])
                                     : (red[4] + red[5] + red[6] + red[7]))
                         * (1.f / (3.f * H));
        __syncthreads();

        const float d0 = v0 - mu, d1 = v1 - mu, d2 = v2 - mu;
        float loc2 = warp_sum(d0 * d0 + d1 * d1 + d2 * d2);
        if ((t & 31) == 0) red[warp] = loc2;
        __syncthreads();
        const float var  = ((sub == 0) ? (red[0] + red[1] + red[2] + red[3])
                                       : (red[4] + red[5] + red[6] + red[7]))
                           * (1.f / (3.f * H));
        const float rstd = rsqrtf(var + LN_EPS);

        const float xn0 = d0 * rstd * gma0 + bta0;
        const float xn1 = d1 * rstd * gma1 + bta1;
        const float xn2 = d2 * rstd * gma2 + bta2;
        sxT[(j)           * HSEG + sl] = silu(xn0);
        sxT[(j + H)       * HSEG + sl] = silu(xn1);
        sxT[(j + 2 * H)   * HSEG + sl] = silu(xn2);
        __syncthreads();
    }

    // ---- x @ W1 for 4 segs, k split across halves ----
    const int k0 = sub * (3 * H / 2);           // 0 or 192
    float4 acc = make_float4(0.f, 0.f, 0.f, 0.f);
    #pragma unroll 4
    for (int kk = 0; kk < 3 * H / 2; ++kk) {
        const int k = k0 + kk;
        const float  w  = W1[k * H + j];
        const float4 sv = *reinterpret_cast<const float4*>(&sxT[k * HSEG]);
        acc.x = fmaf(sv.x, w, acc.x);
        acc.y = fmaf(sv.y, w, acc.y);
        acc.z = fmaf(sv.z, w, acc.z);
        acc.w = fmaf(sv.w, w, acc.w);
    }
    part[sub][j] = acc;
    __syncthreads();

    // ---- SiLU + dot with W2 (half 0 only) ----
    if (sub == 0) {
        const float4 a  = part[0][j];
        const float4 b  = part[1][j];
        const float  bb = b1f[j];
        const float  w2 = W2[j];
        float o0 = silu(a.x + b.x + bb) * w2;
        float o1 = silu(a.y + b.y + bb) * w2;
        float o2 = silu(a.z + b.z + bb) * w2;
        float o3 = silu(a.w + b.w + bb) * w2;
        o0 = warp_sum(o0);
        o1 = warp_sum(o1);
        o2 = warp_sum(o2);
        o3 = warp_sum(o3);
        if ((t & 31) == 0) {
            o_red[warp][0] = o0;
            o_red[warp][1] = o1;
            o_red[warp][2] = o2;
            o_red[warp][3] = o3;
        }
    }
    __syncthreads();

    if (t < HSEG)
        out[blockIdx.x * HSEG + t] =
            o_red[0][t] + o_red[1][t] + o_red[2][t] + o_red[3][t] + b2f[0];
}

// ---------------- launcher ----------------
extern "C" void kernel_launch(void* const* d_in, const int* in_sizes, int n_in,
                              void* d_out, int out_size)
{
    const float* h0  = (const float*)d_in[0];
    const float* h1  = (const float*)d_in[1];
    const float* h2  = (const float*)d_in[2];
    const int*   b0  = (const int*)  d_in[3];
    const int*   b1  = (const int*)  d_in[4];
    const int*   b2  = (const int*)  d_in[5];
    const float* Wg0 = (const float*)d_in[6];
    const float* bg0 = (const float*)d_in[7];
    const float* Wg1 = (const float*)d_in[8];
    const float* bg1 = (const float*)d_in[9];
    const float* Wg2 = (const float*)d_in[10];
    const float* bg2 = (const float*)d_in[11];
    const float* Wp0 = (const float*)d_in[12];
    const float* bp0 = (const float*)d_in[13];
    const float* Wp1 = (const float*)d_in[14];
    const float* bp1 = (const float*)d_in[15];
    const float* Wp2 = (const float*)d_in[16];
    const float* bp2 = (const float*)d_in[17];
    const float* gamma = (const float*)d_in[18];
    const float* beta  = (const float*)d_in[19];
    const float* W1    = (const float*)d_in[20];
    const float* b1f   = (const float*)d_in[21];
    const float* W2    = (const float*)d_in[22];
    const float* b2f   = (const float*)d_in[23];

    const int N0 = in_sizes[3];
    const int N1 = in_sizes[4];
    const int N2 = in_sizes[5];

    // 1. zero segment accumulators
    zero_kernel<<<(RANKS * NSEG * H + 255) / 256, 256>>>();

    // 2. single bandwidth pass over all node features
    dim3 gAgg(384, RANKS);
    agg_kernel<<<gAgg, 256>>>(h0, h1, h2, b0, b1, b2,
                              Wg0, Wg1, Wg2, bg0, bg1, bg2,
                              N0, N1, N2);

    // 3. per-rank pooled projection (seg-tiled)
    dim3 gProj(NSEG / SEGT, RANKS);
    proj_kernel<<<gProj, 512>>>(Wp0, bp0, Wp1, bp1, Wp2, bp2);

    // 4. head (4 segs per block)
    head_kernel<<<NSEG / HSEG, 256>>>(gamma, beta, W1, b1f, W2, b2f, (float*)d_out);
}

// round 7
// speedup vs baseline: 1.1018x; 1.1018x over previous
#include <cuda_runtime.h>
#include <cuda_bf16.h>

#define H     128
#define NSEG  512
#define RANKS 3
#define LN_EPS 1e-5f
#define U     8      // rows per group in agg kernel
#define SEGT  8      // segments per block in proj kernel
#define KC    32     // k-chunk rows staged per step (proj & head)

// ---------------- scratch (no allocations allowed) ----------------
__device__ float g_sum [RANKS * NSEG * H];
__device__ float g_gsum[RANKS * NSEG * H];
__device__ float g_max [RANKS * NSEG * H];
__device__ float g_cnt [RANKS * NSEG];
__device__ float g_r   [RANKS * NSEG * H];

// ---------------- helpers ----------------
__device__ __forceinline__ void atomicMaxF(float* addr, float v) {
    if (v >= 0.f) atomicMax((int*)addr, __float_as_int(v));
    else          atomicMin((unsigned int*)addr, __float_as_uint(v));
}

__device__ __forceinline__ float warp_sum(float v) {
    v += __shfl_xor_sync(0xffffffffu, v, 16);
    v += __shfl_xor_sync(0xffffffffu, v, 8);
    v += __shfl_xor_sync(0xffffffffu, v, 4);
    v += __shfl_xor_sync(0xffffffffu, v, 2);
    v += __shfl_xor_sync(0xffffffffu, v, 1);
    return v;
}

__device__ __forceinline__ float silu(float x) {
    return x / (1.f + __expf(-x));
}

// ---------------- 1. zero accumulators ----------------
__global__ void zero_kernel() {
    int i = blockIdx.x * blockDim.x + threadIdx.x;
    if (i < RANKS * NSEG * H) {
        g_sum[i]  = 0.f;
        g_gsum[i] = 0.f;
        g_max[i]  = __int_as_float(0xff800000);  // -inf
    }
    if (i < RANKS * NSEG) g_cnt[i] = 0.f;
}

// ---------------- 2. single-pass gated multi-aggregation ----------------
// (unchanged from R3/R4 — measured near the DRAM roof)
__global__ __launch_bounds__(256) void agg_kernel(
    const float* __restrict__ h0, const float* __restrict__ h1, const float* __restrict__ h2,
    const int*   __restrict__ b0, const int*   __restrict__ b1, const int*   __restrict__ b2,
    const float* __restrict__ Wg0, const float* __restrict__ Wg1, const float* __restrict__ Wg2,
    const float* __restrict__ bg0, const float* __restrict__ bg1, const float* __restrict__ bg2,
    int N0, int N1, int N2)
{
    const int rank = blockIdx.y;
    const float* h;  const int* b;  const float* Wg;  float bg;  int N;
    if (rank == 0)      { h = h0; b = b0; Wg = Wg0; bg = bg0[0]; N = N0; }
    else if (rank == 1) { h = h1; b = b1; Wg = Wg1; bg = bg1[0]; N = N1; }
    else                { h = h2; b = b2; Wg = Wg2; bg = bg2[0]; N = N2; }

    const int lane          = threadIdx.x & 31;
    const int warpsPerBlock = blockDim.x >> 5;
    const int gw            = blockIdx.x * warpsPerBlock + (threadIdx.x >> 5);
    const int totalWarps    = gridDim.x * warpsPerBlock;
    const int chunk         = (N + totalWarps - 1) / totalWarps;
    const int start         = gw * chunk;
    const int end           = min(start + chunk, N);
    if (start >= end) return;

    const float4 wg  = reinterpret_cast<const float4*>(Wg)[lane];
    const float  NEG = __int_as_float(0xff800000);

    float4 s  = make_float4(0.f, 0.f, 0.f, 0.f);
    float4 gs = make_float4(0.f, 0.f, 0.f, 0.f);
    float4 mx = make_float4(NEG, NEG, NEG, NEG);
    float  cnt = 0.f;
    int    cur = __ldg(&b[start]);

    #define FLUSH()                                                          \
    do {                                                                     \
        const int _base = (rank * NSEG + cur) * H + lane * 4;                \
        atomicAdd(&g_sum [_base + 0], s.x);  atomicAdd(&g_sum [_base + 1], s.y);  \
        atomicAdd(&g_sum [_base + 2], s.z);  atomicAdd(&g_sum [_base + 3], s.w);  \
        atomicAdd(&g_gsum[_base + 0], gs.x); atomicAdd(&g_gsum[_base + 1], gs.y); \
        atomicAdd(&g_gsum[_base + 2], gs.z); atomicAdd(&g_gsum[_base + 3], gs.w); \
        atomicMaxF(&g_max[_base + 0], mx.x); atomicMaxF(&g_max[_base + 1], mx.y); \
        atomicMaxF(&g_max[_base + 2], mx.z); atomicMaxF(&g_max[_base + 3], mx.w); \
        if (lane == 0) atomicAdd(&g_cnt[rank * NSEG + cur], cnt);            \
        s  = make_float4(0.f, 0.f, 0.f, 0.f);                                \
        gs = make_float4(0.f, 0.f, 0.f, 0.f);                                \
        mx = make_float4(NEG, NEG, NEG, NEG);                                \
        cnt = 0.f;                                                           \
    } while (0)

    int row = start;

    for (; row + U <= end; row += U) {
        float4 hv[U];
        int    sg[U];
        float  p[U];
        #pragma unroll
        for (int i = 0; i < U; ++i) {
            hv[i] = reinterpret_cast<const float4*>(h + (size_t)(row + i) * H)[lane];
            sg[i] = __ldg(&b[row + i]);
        }
        #pragma unroll
        for (int i = 0; i < U; ++i)
            p[i] = hv[i].x * wg.x + hv[i].y * wg.y + hv[i].z * wg.z + hv[i].w * wg.w;

        #pragma unroll
        for (int off = 16; off; off >>= 1) {
            #pragma unroll
            for (int i = 0; i < U; ++i)
                p[i] += __shfl_xor_sync(0xffffffffu, p[i], off);
        }

        #pragma unroll
        for (int i = 0; i < U; ++i) {
            if (sg[i] != cur) { FLUSH(); cur = sg[i]; }
            const float g = 1.f / (1.f + __expf(-(p[i] + bg)));
            s.x += hv[i].x; s.y += hv[i].y; s.z += hv[i].z; s.w += hv[i].w;
            gs.x = fmaf(g, hv[i].x, gs.x); gs.y = fmaf(g, hv[i].y, gs.y);
            gs.z = fmaf(g, hv[i].z, gs.z); gs.w = fmaf(g, hv[i].w, gs.w);
            mx.x = fmaxf(mx.x, hv[i].x);  mx.y = fmaxf(mx.y, hv[i].y);
            mx.z = fmaxf(mx.z, hv[i].z);  mx.w = fmaxf(mx.w, hv[i].w);
            cnt += 1.f;
        }
    }

    for (; row < end; ++row) {
        float4 hv = reinterpret_cast<const float4*>(h + (size_t)row * H)[lane];
        int    sg = __ldg(&b[row]);
        if (sg != cur) { FLUSH(); cur = sg; }
        float p = hv.x * wg.x + hv.y * wg.y + hv.z * wg.z + hv.w * wg.w;
        p = warp_sum(p);
        const float g = 1.f / (1.f + __expf(-(p + bg)));
        s.x += hv.x; s.y += hv.y; s.z += hv.z; s.w += hv.w;
        gs.x = fmaf(g, hv.x, gs.x); gs.y = fmaf(g, hv.y, gs.y);
        gs.z = fmaf(g, hv.z, gs.z); gs.w = fmaf(g, hv.w, gs.w);
        mx.x = fmaxf(mx.x, hv.x);  mx.y = fmaxf(mx.y, hv.y);
        mx.z = fmaxf(mx.z, hv.z);  mx.w = fmaxf(mx.w, hv.w);
        cnt += 1.f;
    }

    FLUSH();
    #undef FLUSH
}

// ---------------- 3. per-rank projection: agg[B,4H] @ Wp[4H,H] + bp ----------------
// Grid (64 seg-groups, 2 j-halves, 3 ranks) = 384 blocks, 256 threads.
// Wp streamed through shared in double-buffered KC=32-row chunks.
__global__ __launch_bounds__(256) void proj_kernel(
    const float* __restrict__ Wp0, const float* __restrict__ bp0,
    const float* __restrict__ Wp1, const float* __restrict__ bp1,
    const float* __restrict__ Wp2, const float* __restrict__ bp2)
{
    const int segBase = blockIdx.x * SEGT;
    const int jhalf   = blockIdx.y;          // 0 or 1
    const int rank    = blockIdx.z;
    const int t       = threadIdx.x;

    const float* Wp = (rank == 0) ? Wp0 : (rank == 1) ? Wp1 : Wp2;
    const float* bp = (rank == 0) ? bp0 : (rank == 1) ? bp1 : bp2;

    __shared__ __align__(16) float saggT[4 * H * SEGT];   // [k][seg]  16 KB
    __shared__ __align__(16) float sW[2][KC][64];         // 2 × 8 KB

    // stage transposed agg vectors (each block loads 8 segs x 512 k)
    for (int idx = t; idx < SEGT * 4 * H; idx += 256) {
        const int sl  = idx >> 9;            // idx / 512
        const int k   = idx & 511;
        const int seg = segBase + sl;
        const int gb  = (rank * NSEG + seg) * H;
        const float cnt = g_cnt[rank * NSEG + seg];
        const int q  = k >> 7;
        const int jj = k & 127;
        float val;
        if (q == 0)      val = g_sum[gb + jj];
        else if (q == 1) val = g_sum[gb + jj] / fmaxf(cnt, 1.f);
        else if (q == 2) { const float mv = g_max[gb + jj]; val = (cnt > 0.f) ? mv : 0.f; }
        else             val = g_gsum[gb + jj];
        saggT[k * SEGT + sl] = val;
    }

    // staging mapping: thread t loads 8 floats of a KC x 64 chunk
    const int lr = t >> 3;                   // 0..31 chunk row
    const int lc = (t & 7) * 8;              // col 0..56 step 8
    const int wcol = jhalf * 64;

    float4 pre0, pre1;
    {   // prefetch chunk 0
        const float* src = Wp + (0 + lr) * H + wcol + lc;
        pre0 = *reinterpret_cast<const float4*>(src);
        pre1 = *reinterpret_cast<const float4*>(src + 4);
    }
    *reinterpret_cast<float4*>(&sW[0][lr][lc])     = pre0;
    *reinterpret_cast<float4*>(&sW[0][lr][lc + 4]) = pre1;

    const int jj   = t & 63;                 // output column within half
    const int sgrp = t >> 6;                 // 0..3 -> seg pair
    const int s0   = sgrp * 2;

    float a0 = 0.f, a1 = 0.f;

    const int NCH = 4 * H / KC;              // 16 chunks
    for (int c = 0; c < NCH; ++c) {
        __syncthreads();                     // chunk c staged; buffer c+1 free
        if (c + 1 < NCH) {
            const float* src = Wp + ((c + 1) * KC + lr) * H + wcol + lc;
            pre0 = *reinterpret_cast<const float4*>(src);
            pre1 = *reinterpret_cast<const float4*>(src + 4);
        }
        const int k0 = c * KC;
        const float (*w)[64] = sW[c & 1];
        #pragma unroll
        for (int kc = 0; kc < KC; ++kc) {
            const float  wv = w[kc][jj];
            const float2 sv = *reinterpret_cast<const float2*>(&saggT[(k0 + kc) * SEGT + s0]);
            a0 = fmaf(sv.x, wv, a0);
            a1 = fmaf(sv.y, wv, a1);
        }
        if (c + 1 < NCH) {
            *reinterpret_cast<float4*>(&sW[(c + 1) & 1][lr][lc])     = pre0;
            *reinterpret_cast<float4*>(&sW[(c + 1) & 1][lr][lc + 4]) = pre1;
        }
    }

    const int j  = wcol + jj;
    const float bj = bp[j];
    const int gb = (rank * NSEG + segBase + s0) * H + j;
    g_r[gb]     = a0 + bj;
    g_r[gb + H] = a1 + bj;
}

// ---------------- 4. head: concat -> LayerNorm -> SiLU -> W1 -> SiLU -> W2 ----------------
// Grid 256 blocks, 256 threads; each 128-thread half owns one segment (full k).
// W1 streamed through shared in double-buffered KC=32-row chunks.
__global__ __launch_bounds__(256) void head_kernel(
    const float* __restrict__ gamma, const float* __restrict__ beta,
    const float* __restrict__ W1,    const float* __restrict__ b1f,
    const float* __restrict__ W2,    const float* __restrict__ b2f,
    float* __restrict__ out)
{
    const int t    = threadIdx.x;
    const int j    = t & (H - 1);
    const int sub  = t >> 7;                 // 0 or 1 -> local segment
    const int warp = t >> 5;                 // 0..7
    const int seg  = blockIdx.x * 2 + sub;

    __shared__ __align__(16) float sx[2][3 * H];     // per-half activations
    __shared__ __align__(16) float sW1[2][KC][H];    // 2 × 16 KB
    __shared__ float red[8];

    // ---- LayerNorm + SiLU (each half independent) ----
    const float v0 = g_r[(0 * NSEG + seg) * H + j];
    const float v1 = g_r[(1 * NSEG + seg) * H + j];
    const float v2 = g_r[(2 * NSEG + seg) * H + j];

    float loc = warp_sum(v0 + v1 + v2);
    if ((t & 31) == 0) red[warp] = loc;
    __syncthreads();
    const float mu = ((sub == 0) ? (red[0] + red[1] + red[2] + red[3])
                                 : (red[4] + red[5] + red[6] + red[7]))
                     * (1.f / (3.f * H));
    __syncthreads();

    const float d0 = v0 - mu, d1 = v1 - mu, d2 = v2 - mu;
    float loc2 = warp_sum(d0 * d0 + d1 * d1 + d2 * d2);
    if ((t & 31) == 0) red[warp] = loc2;
    __syncthreads();
    const float var  = ((sub == 0) ? (red[0] + red[1] + red[2] + red[3])
                                   : (red[4] + red[5] + red[6] + red[7]))
                       * (1.f / (3.f * H));
    const float rstd = rsqrtf(var + LN_EPS);

    {
        const float xn0 = d0 * rstd * gamma[j]         + beta[j];
        const float xn1 = d1 * rstd * gamma[H + j]     + beta[H + j];
        const float xn2 = d2 * rstd * gamma[2 * H + j] + beta[2 * H + j];
        sx[sub][j]         = silu(xn0);
        sx[sub][H + j]     = silu(xn1);
        sx[sub][2 * H + j] = silu(xn2);
    }

    // staging mapping: thread t loads 16 floats of a KC x 128 chunk
    const int lr = t >> 3;                   // 0..31 chunk row
    const int lc = (t & 7) * 16;             // col 0..112 step 16

    float4 pre0, pre1, pre2, pre3;
    {
        const float* src = W1 + (0 + lr) * H + lc;
        pre0 = *reinterpret_cast<const float4*>(src);
        pre1 = *reinterpret_cast<const float4*>(src + 4);
        pre2 = *reinterpret_cast<const float4*>(src + 8);
        pre3 = *reinterpret_cast<const float4*>(src + 12);
    }
    *reinterpret_cast<float4*>(&sW1[0][lr][lc])      = pre0;
    *reinterpret_cast<float4*>(&sW1[0][lr][lc + 4])  = pre1;
    *reinterpret_cast<float4*>(&sW1[0][lr][lc + 8])  = pre2;
    *reinterpret_cast<float4*>(&sW1[0][lr][lc + 12]) = pre3;

    float acc = 0.f;
    const int NCH = 3 * H / KC;              // 12 chunks
    for (int c = 0; c < NCH; ++c) {
        __syncthreads();
        if (c + 1 < NCH) {
            const float* src = W1 + ((c + 1) * KC + lr) * H + lc;
            pre0 = *reinterpret_cast<const float4*>(src);
            pre1 = *reinterpret_cast<const float4*>(src + 4);
            pre2 = *reinterpret_cast<const float4*>(src + 8);
            pre3 = *reinterpret_cast<const float4*>(src + 12);
        }
        const int k0 = c * KC;
        const float (*w)[H] = sW1[c & 1];
        const float* sxs = sx[sub] + k0;
        #pragma unroll
        for (int kc = 0; kc < KC; ++kc)
            acc = fmaf(sxs[kc], w[kc][j], acc);
        if (c + 1 < NCH) {
            *reinterpret_cast<float4*>(&sW1[(c + 1) & 1][lr][lc])      = pre0;
            *reinterpret_cast<float4*>(&sW1[(c + 1) & 1][lr][lc + 4])  = pre1;
            *reinterpret_cast<float4*>(&sW1[(c + 1) & 1][lr][lc + 8])  = pre2;
            *reinterpret_cast<float4*>(&sW1[(c + 1) & 1][lr][lc + 12]) = pre3;
        }
    }

    // SiLU -> dot with W2 -> out[seg]
    const float x2 = silu(acc + b1f[j]);
    float o = warp_sum(x2 * W2[j]);
    if ((t & 31) == 0) red[warp] = o;
    __syncthreads();
    if ((t & 127) == 0)
        out[seg] = ((sub == 0) ? (red[0] + red[1] + red[2] + red[3])
                               : (red[4] + red[5] + red[6] + red[7])) + b2f[0];
}

// ---------------- launcher ----------------
extern "C" void kernel_launch(void* const* d_in, const int* in_sizes, int n_in,
                              void* d_out, int out_size)
{
    const float* h0  = (const float*)d_in[0];
    const float* h1  = (const float*)d_in[1];
    const float* h2  = (const float*)d_in[2];
    const int*   b0  = (const int*)  d_in[3];
    const int*   b1  = (const int*)  d_in[4];
    const int*   b2  = (const int*)  d_in[5];
    const float* Wg0 = (const float*)d_in[6];
    const float* bg0 = (const float*)d_in[7];
    const float* Wg1 = (const float*)d_in[8];
    const float* bg1 = (const float*)d_in[9];
    const float* Wg2 = (const float*)d_in[10];
    const float* bg2 = (const float*)d_in[11];
    const float* Wp0 = (const float*)d_in[12];
    const float* bp0 = (const float*)d_in[13];
    const float* Wp1 = (const float*)d_in[14];
    const float* bp1 = (const float*)d_in[15];
    const float* Wp2 = (const float*)d_in[16];
    const float* bp2 = (const float*)d_in[17];
    const float* gamma = (const float*)d_in[18];
    const float* beta  = (const float*)d_in[19];
    const float* W1    = (const float*)d_in[20];
    const float* b1f   = (const float*)d_in[21];
    const float* W2    = (const float*)d_in[22];
    const float* b2f   = (const float*)d_in[23];

    const int N0 = in_sizes[3];
    const int N1 = in_sizes[4];
    const int N2 = in_sizes[5];

    // 1. zero segment accumulators
    zero_kernel<<<(RANKS * NSEG * H + 255) / 256, 256>>>();

    // 2. single bandwidth pass over all node features
    dim3 gAgg(384, RANKS);
    agg_kernel<<<gAgg, 256>>>(h0, h1, h2, b0, b1, b2,
                              Wg0, Wg1, Wg2, bg0, bg1, bg2,
                              N0, N1, N2);

    // 3. per-rank pooled projection (seg-tiled, shared-staged Wp)
    dim3 gProj(NSEG / SEGT, 2, RANKS);
    proj_kernel<<<gProj, 256>>>(Wp0, bp0, Wp1, bp1, Wp2, bp2);

    // 4. head (2 segs per block, shared-staged W1)
    head_kernel<<<NSEG / 2, 256>>>(gamma, beta, W1, b1f, W2, b2f, (float*)d_out);
}

// round 9
// speedup vs baseline: 1.1238x; 1.0200x over previous
#include <cuda_runtime.h>
#include <cuda_bf16.h>

#define H     128
#define NSEG  512
#define RANKS 3
#define LN_EPS 1e-5f
#define U     8      // rows per group in agg kernel
#define SEGT  8      // segments per block in proj kernel

// ---------------- scratch (no allocations allowed) ----------------
__device__ float g_sum [RANKS * NSEG * H];
__device__ float g_gsum[RANKS * NSEG * H];
__device__ float g_max [RANKS * NSEG * H];
__device__ float g_cnt [RANKS * NSEG];
__device__ float g_r   [RANKS * NSEG * H];

// ---------------- helpers ----------------
__device__ __forceinline__ void atomicMaxF(float* addr, float v) {
    if (v >= 0.f) atomicMax((int*)addr, __float_as_int(v));
    else          atomicMin((unsigned int*)addr, __float_as_uint(v));
}

__device__ __forceinline__ float warp_sum(float v) {
    v += __shfl_xor_sync(0xffffffffu, v, 16);
    v += __shfl_xor_sync(0xffffffffu, v, 8);
    v += __shfl_xor_sync(0xffffffffu, v, 4);
    v += __shfl_xor_sync(0xffffffffu, v, 2);
    v += __shfl_xor_sync(0xffffffffu, v, 1);
    return v;
}

__device__ __forceinline__ float silu(float x) {
    return x / (1.f + __expf(-x));
}

// ---------------- 1. zero accumulators + seed g_r with proj bias ----------------
__global__ void zero_kernel(const float* __restrict__ bp0,
                            const float* __restrict__ bp1,
                            const float* __restrict__ bp2) {
    int i = blockIdx.x * blockDim.x + threadIdx.x;
    if (i < RANKS * NSEG * H) {
        g_sum[i]  = 0.f;
        g_gsum[i] = 0.f;
        g_max[i]  = __int_as_float(0xff800000);  // -inf
        const int rank = i / (NSEG * H);
        const int j    = i & (H - 1);
        const float* bp = (rank == 0) ? bp0 : (rank == 1) ? bp1 : bp2;
        g_r[i] = bp[j];
    }
    if (i < RANKS * NSEG) g_cnt[i] = 0.f;
}

// ---------------- 2. single-pass gated multi-aggregation ----------------
// (unchanged — warp-per-chunk, 8-row groups, interleaved butterflies)
__global__ __launch_bounds__(256) void agg_kernel(
    const float* __restrict__ h0, const float* __restrict__ h1, const float* __restrict__ h2,
    const int*   __restrict__ b0, const int*   __restrict__ b1, const int*   __restrict__ b2,
    const float* __restrict__ Wg0, const float* __restrict__ Wg1, const float* __restrict__ Wg2,
    const float* __restrict__ bg0, const float* __restrict__ bg1, const float* __restrict__ bg2,
    int N0, int N1, int N2)
{
    const int rank = blockIdx.y;
    const float* h;  const int* b;  const float* Wg;  float bg;  int N;
    if (rank == 0)      { h = h0; b = b0; Wg = Wg0; bg = bg0[0]; N = N0; }
    else if (rank == 1) { h = h1; b = b1; Wg = Wg1; bg = bg1[0]; N = N1; }
    else                { h = h2; b = b2; Wg = Wg2; bg = bg2[0]; N = N2; }

    const int lane          = threadIdx.x & 31;
    const int warpsPerBlock = blockDim.x >> 5;
    const int gw            = blockIdx.x * warpsPerBlock + (threadIdx.x >> 5);
    const int totalWarps    = gridDim.x * warpsPerBlock;
    const int chunk         = (N + totalWarps - 1) / totalWarps;
    const int start         = gw * chunk;
    const int end           = min(start + chunk, N);
    if (start >= end) return;

    const float4 wg  = reinterpret_cast<const float4*>(Wg)[lane];
    const float  NEG = __int_as_float(0xff800000);

    float4 s  = make_float4(0.f, 0.f, 0.f, 0.f);
    float4 gs = make_float4(0.f, 0.f, 0.f, 0.f);
    float4 mx = make_float4(NEG, NEG, NEG, NEG);
    float  cnt = 0.f;
    int    cur = __ldg(&b[start]);

    #define FLUSH()                                                          \
    do {                                                                     \
        const int _base = (rank * NSEG + cur) * H + lane * 4;                \
        atomicAdd(&g_sum [_base + 0], s.x);  atomicAdd(&g_sum [_base + 1], s.y);  \
        atomicAdd(&g_sum [_base + 2], s.z);  atomicAdd(&g_sum [_base + 3], s.w);  \
        atomicAdd(&g_gsum[_base + 0], gs.x); atomicAdd(&g_gsum[_base + 1], gs.y); \
        atomicAdd(&g_gsum[_base + 2], gs.z); atomicAdd(&g_gsum[_base + 3], gs.w); \
        atomicMaxF(&g_max[_base + 0], mx.x); atomicMaxF(&g_max[_base + 1], mx.y); \
        atomicMaxF(&g_max[_base + 2], mx.z); atomicMaxF(&g_max[_base + 3], mx.w); \
        if (lane == 0) atomicAdd(&g_cnt[rank * NSEG + cur], cnt);            \
        s  = make_float4(0.f, 0.f, 0.f, 0.f);                                \
        gs = make_float4(0.f, 0.f, 0.f, 0.f);                                \
        mx = make_float4(NEG, NEG, NEG, NEG);                                \
        cnt = 0.f;                                                           \
    } while (0)

    int row = start;

    for (; row + U <= end; row += U) {
        float4 hv[U];
        int    sg[U];
        float  p[U];
        #pragma unroll
        for (int i = 0; i < U; ++i) {
            hv[i] = reinterpret_cast<const float4*>(h + (size_t)(row + i) * H)[lane];
            sg[i] = __ldg(&b[row + i]);
        }
        #pragma unroll
        for (int i = 0; i < U; ++i)
            p[i] = hv[i].x * wg.x + hv[i].y * wg.y + hv[i].z * wg.z + hv[i].w * wg.w;

        #pragma unroll
        for (int off = 16; off; off >>= 1) {
            #pragma unroll
            for (int i = 0; i < U; ++i)
                p[i] += __shfl_xor_sync(0xffffffffu, p[i], off);
        }

        #pragma unroll
        for (int i = 0; i < U; ++i) {
            if (sg[i] != cur) { FLUSH(); cur = sg[i]; }
            const float g = 1.f / (1.f + __expf(-(p[i] + bg)));
            s.x += hv[i].x; s.y += hv[i].y; s.z += hv[i].z; s.w += hv[i].w;
            gs.x = fmaf(g, hv[i].x, gs.x); gs.y = fmaf(g, hv[i].y, gs.y);
            gs.z = fmaf(g, hv[i].z, gs.z); gs.w = fmaf(g, hv[i].w, gs.w);
            mx.x = fmaxf(mx.x, hv[i].x);  mx.y = fmaxf(mx.y, hv[i].y);
            mx.z = fmaxf(mx.z, hv[i].z);  mx.w = fmaxf(mx.w, hv[i].w);
            cnt += 1.f;
        }
    }

    for (; row < end; ++row) {
        float4 hv = reinterpret_cast<const float4*>(h + (size_t)row * H)[lane];
        int    sg = __ldg(&b[row]);
        if (sg != cur) { FLUSH(); cur = sg; }
        float p = hv.x * wg.x + hv.y * wg.y + hv.z * wg.z + hv.w * wg.w;
        p = warp_sum(p);
        const float g = 1.f / (1.f + __expf(-(p + bg)));
        s.x += hv.x; s.y += hv.y; s.z += hv.z; s.w += hv.w;
        gs.x = fmaf(g, hv.x, gs.x); gs.y = fmaf(g, hv.y, gs.y);
        gs.z = fmaf(g, hv.z, gs.z); gs.w = fmaf(g, hv.w, gs.w);
        mx.x = fmaxf(mx.x, hv.x);  mx.y = fmaxf(mx.y, hv.y);
        mx.z = fmaxf(mx.z, hv.z);  mx.w = fmaxf(mx.w, hv.w);
        cnt += 1.f;
    }

    FLUSH();
    #undef FLUSH
}

// ---------------- 3. projection, split-k by aggregate type ----------------
// Grid (64 seg-groups, 4 k-quarters, 3 ranks) = 768 blocks, 256 threads.
// k-quarter q maps exactly to aggregate type: 0=sum, 1=mean, 2=max, 3=gsum.
// Each block: 128-deep dot for 8 segs x 128 j, 4 independent accumulators,
// atomicAdd partials into g_r (pre-seeded with bp in zero_kernel).
__global__ __launch_bounds__(256) void proj_kernel(
    const float* __restrict__ Wp0,
    const float* __restrict__ Wp1,
    const float* __restrict__ Wp2)
{
    const int segBase = blockIdx.x * SEGT;
    const int q       = blockIdx.y;          // 0..3
    const int rank    = blockIdx.z;
    const int t       = threadIdx.x;

    const float* Wp = (rank == 0) ? Wp0 : (rank == 1) ? Wp1 : Wp2;

    __shared__ float sa[SEGT][H];            // 4 KB: one aggregate for 8 segs

    // stage aggregate q for the 8 segments
    for (int idx = t; idx < SEGT * H; idx += 256) {
        const int sl  = idx >> 7;
        const int jj  = idx & (H - 1);
        const int seg = segBase + sl;
        const int gb  = (rank * NSEG + seg) * H + jj;
        float val;
        if (q == 0)      val = g_sum[gb];
        else if (q == 1) val = g_sum[gb] / fmaxf(g_cnt[rank * NSEG + seg], 1.f);
        else if (q == 2) { const float mv = g_max[gb];
                           val = (g_cnt[rank * NSEG + seg] > 0.f) ? mv : 0.f; }
        else             val = g_gsum[gb];
        sa[sl][jj] = val;
    }
    __syncthreads();

    const int j   = t & (H - 1);
    const int sub = t >> 7;                  // 0/1
    const int s0  = sub * 4;                 // local segs s0..s0+3

    const float* wq = Wp + q * H * H + j;    // rows q*128..q*128+127, column j
    float a0 = 0.f, a1 = 0.f, a2 = 0.f, a3 = 0.f;
    #pragma unroll 4
    for (int k = 0; k < H; ++k) {
        const float wv = __ldg(&wq[k * H]);
        a0 = fmaf(sa[s0 + 0][k], wv, a0);
        a1 = fmaf(sa[s0 + 1][k], wv, a1);
        a2 = fmaf(sa[s0 + 2][k], wv, a2);
        a3 = fmaf(sa[s0 + 3][k], wv, a3);
    }

    const int gb = (rank * NSEG + segBase + s0) * H + j;
    atomicAdd(&g_r[gb],         a0);
    atomicAdd(&g_r[gb + H],     a1);
    atomicAdd(&g_r[gb + 2 * H], a2);
    atomicAdd(&g_r[gb + 3 * H], a3);
}

// ---------------- 4. head (R3 measured-best version) ----------------
// 512 blocks, 256 threads: half 0 does LN; both halves split the 3H matvec.
__global__ __launch_bounds__(256) void head_kernel(
    const float* __restrict__ gamma, const float* __restrict__ beta,
    const float* __restrict__ W1,    const float* __restrict__ b1f,
    const float* __restrict__ W2,    const float* __restrict__ b2f,
    float* __restrict__ out)
{
    const int seg  = blockIdx.x;
    const int t    = threadIdx.x;
    const int j    = t & (H - 1);
    const int half = t >> 7;

    __shared__ float sx[3 * H];
    __shared__ float part[256];
    __shared__ float red[8];

    float v0 = 0.f, v1 = 0.f, v2 = 0.f;
    if (half == 0) {
        v0 = g_r[(0 * NSEG + seg) * H + j];
        v1 = g_r[(1 * NSEG + seg) * H + j];
        v2 = g_r[(2 * NSEG + seg) * H + j];
    }

    // mean (half-1 warps contribute 0)
    float loc = warp_sum(v0 + v1 + v2);
    if ((t & 31) == 0) red[t >> 5] = loc;
    __syncthreads();
    const float mu = (red[0] + red[1] + red[2] + red[3] +
                      red[4] + red[5] + red[6] + red[7]) * (1.f / (3.f * H));
    __syncthreads();

    // variance
    const float d0 = v0 - mu, d1 = v1 - mu, d2 = v2 - mu;
    float loc2 = warp_sum(half == 0 ? (d0 * d0 + d1 * d1 + d2 * d2) : 0.f);
    if ((t & 31) == 0) red[t >> 5] = loc2;
    __syncthreads();
    const float var  = (red[0] + red[1] + red[2] + red[3] +
                        red[4] + red[5] + red[6] + red[7]) * (1.f / (3.f * H));
    const float rstd = rsqrtf(var + LN_EPS);
    __syncthreads();

    if (half == 0) {
        float xn0 = d0 * rstd * gamma[j]         + beta[j];
        float xn1 = d1 * rstd * gamma[H + j]     + beta[H + j];
        float xn2 = d2 * rstd * gamma[2 * H + j] + beta[2 * H + j];
        sx[j]         = silu(xn0);
        sx[H + j]     = silu(xn1);
        sx[2 * H + j] = silu(xn2);
    }
    __syncthreads();

    // x @ W1 (+b1f): each half sums 192 of the 384 k's with 4 accumulators
    const int k0 = half * 192;
    float a0 = 0.f, a1 = 0.f, a2 = 0.f, a3 = 0.f;
    #pragma unroll 4
    for (int k = 0; k < 192; k += 4) {
        a0 = fmaf(sx[k0 + k + 0], W1[(k0 + k + 0) * H + j], a0);
        a1 = fmaf(sx[k0 + k + 1], W1[(k0 + k + 1) * H + j], a1);
        a2 = fmaf(sx[k0 + k + 2], W1[(k0 + k + 2) * H + j], a2);
        a3 = fmaf(sx[k0 + k + 3], W1[(k0 + k + 3) * H + j], a3);
    }
    part[t] = (a0 + a1) + (a2 + a3);
    __syncthreads();

    // SiLU -> dot with W2 -> out[seg]   (half 0 only)
    float o = 0.f;
    if (half == 0) {
        const float acc = part[j] + part[H + j] + b1f[j];
        const float x2  = silu(acc);
        o = x2 * W2[j];
    }
    o = warp_sum(o);
    if ((t & 31) == 0) red[t >> 5] = o;
    __syncthreads();
    if (t == 0)
        out[seg] = red[0] + red[1] + red[2] + red[3] + b2f[0];
}

// ---------------- launcher ----------------
extern "C" void kernel_launch(void* const* d_in, const int* in_sizes, int n_in,
                              void* d_out, int out_size)
{
    const float* h0  = (const float*)d_in[0];
    const float* h1  = (const float*)d_in[1];
    const float* h2  = (const float*)d_in[2];
    const int*   b0  = (const int*)  d_in[3];
    const int*   b1  = (const int*)  d_in[4];
    const int*   b2  = (const int*)  d_in[5];
    const float* Wg0 = (const float*)d_in[6];
    const float* bg0 = (const float*)d_in[7];
    const float* Wg1 = (const float*)d_in[8];
    const float* bg1 = (const float*)d_in[9];
    const float* Wg2 = (const float*)d_in[10];
    const float* bg2 = (const float*)d_in[11];
    const float* Wp0 = (const float*)d_in[12];
    const float* bp0 = (const float*)d_in[13];
    const float* Wp1 = (const float*)d_in[14];
    const float* bp1 = (const float*)d_in[15];
    const float* Wp2 = (const float*)d_in[16];
    const float* bp2 = (const float*)d_in[17];
    const float* gamma = (const float*)d_in[18];
    const float* beta  = (const float*)d_in[19];
    const float* W1    = (const float*)d_in[20];
    const float* b1f   = (const float*)d_in[21];
    const float* W2    = (const float*)d_in[22];
    const float* b2f   = (const float*)d_in[23];

    const int N0 = in_sizes[3];
    const int N1 = in_sizes[4];
    const int N2 = in_sizes[5];

    // 1. zero segment accumulators; seed g_r with bp
    zero_kernel<<<(RANKS * NSEG * H + 255) / 256, 256>>>(bp0, bp1, bp2);

    // 2. single bandwidth pass over all node features
    dim3 gAgg(384, RANKS);
    agg_kernel<<<gAgg, 256>>>(h0, h1, h2, b0, b1, b2,
                              Wg0, Wg1, Wg2, bg0, bg1, bg2,
                              N0, N1, N2);

    // 3. projection: split-k by aggregate type, atomic accumulation
    dim3 gProj(NSEG / SEGT, 4, RANKS);
    proj_kernel<<<gProj, 256>>>(Wp0, Wp1, Wp2);

    // 4. head (one seg per block — measured-best configuration)
    head_kernel<<<NSEG, 256>>>(gamma, beta, W1, b1f, W2, b2f, (float*)d_out);
}

// round 11
// speedup vs baseline: 1.1956x; 1.0638x over previous
#include <cuda_runtime.h>
#include <cuda_bf16.h>

#define H     128
#define NSEG  512
#define RANKS 3
#define LN_EPS 1e-5f
#define U     8      // rows per group in agg kernel
#define SEGT  8      // segments per block in proj kernel
#define AGG_BLOCKS 444   // 3 blocks/SM x 148 SMs -> single wave

// ---------------- scratch (no allocations allowed) ----------------
__device__ float g_sum [RANKS * NSEG * H];
__device__ float g_gsum[RANKS * NSEG * H];
__device__ float g_max [RANKS * NSEG * H];
__device__ float g_cnt [RANKS * NSEG];
__device__ float g_r   [RANKS * NSEG * H];

// ---------------- helpers ----------------
__device__ __forceinline__ void atomicMaxF(float* addr, float v) {
    if (v >= 0.f) atomicMax((int*)addr, __float_as_int(v));
    else          atomicMin((unsigned int*)addr, __float_as_uint(v));
}

__device__ __forceinline__ float warp_sum(float v) {
    v += __shfl_xor_sync(0xffffffffu, v, 16);
    v += __shfl_xor_sync(0xffffffffu, v, 8);
    v += __shfl_xor_sync(0xffffffffu, v, 4);
    v += __shfl_xor_sync(0xffffffffu, v, 2);
    v += __shfl_xor_sync(0xffffffffu, v, 1);
    return v;
}

__device__ __forceinline__ float silu(float x) {
    return x / (1.f + __expf(-x));
}

// ---------------- 1. zero accumulators + seed g_r with proj bias ----------------
__global__ void zero_kernel(const float* __restrict__ bp0,
                            const float* __restrict__ bp1,
                            const float* __restrict__ bp2) {
    int i = blockIdx.x * blockDim.x + threadIdx.x;
    if (i < RANKS * NSEG * H) {
        g_sum[i]  = 0.f;
        g_gsum[i] = 0.f;
        g_max[i]  = __int_as_float(0xff800000);  // -inf
        const int rank = i / (NSEG * H);
        const int j    = i & (H - 1);
        const float* bp = (rank == 0) ? bp0 : (rank == 1) ? bp1 : bp2;
        g_r[i] = bp[j];
    }
    if (i < RANKS * NSEG) g_cnt[i] = 0.f;
}

// ---------------- 2. single-pass gated multi-aggregation ----------------
// Flat proportional grid (single balanced wave). Warp-per-contiguous-chunk,
// 8-row groups, interleaved butterflies, group-uniform boundary fast path.
__global__ __launch_bounds__(256, 3) void agg_kernel(
    const float* __restrict__ h0, const float* __restrict__ h1, const float* __restrict__ h2,
    const int*   __restrict__ b0, const int*   __restrict__ b1, const int*   __restrict__ b2,
    const float* __restrict__ Wg0, const float* __restrict__ Wg1, const float* __restrict__ Wg2,
    const float* __restrict__ bg0, const float* __restrict__ bg1, const float* __restrict__ bg2,
    int N0, int N1, int N2, int g0, int g1)
{
    // flat block -> (rank, local block)
    const int bx = blockIdx.x;
    int rank, lbx, nBlocks;
    if (bx < g0)            { rank = 0; lbx = bx;            nBlocks = g0; }
    else if (bx < g0 + g1)  { rank = 1; lbx = bx - g0;       nBlocks = g1; }
    else                    { rank = 2; lbx = bx - g0 - g1;  nBlocks = gridDim.x - g0 - g1; }

    const float* h;  const int* b;  const float* Wg;  float bg;  int N;
    if (rank == 0)      { h = h0; b = b0; Wg = Wg0; bg = bg0[0]; N = N0; }
    else if (rank == 1) { h = h1; b = b1; Wg = Wg1; bg = bg1[0]; N = N1; }
    else                { h = h2; b = b2; Wg = Wg2; bg = bg2[0]; N = N2; }

    const int lane       = threadIdx.x & 31;
    const int gw         = lbx * 8 + (threadIdx.x >> 5);     // 8 warps/block
    const int totalWarps = nBlocks * 8;
    int chunk            = (N + totalWarps - 1) / totalWarps;
    chunk                = (chunk + U - 1) & ~(U - 1);       // align to U for int4 b loads
    const int start      = gw * chunk;
    const int end        = min(start + chunk, N);
    if (start >= end) return;

    const float4 wg  = reinterpret_cast<const float4*>(Wg)[lane];
    const float  NEG = __int_as_float(0xff800000);

    float4 s  = make_float4(0.f, 0.f, 0.f, 0.f);
    float4 gs = make_float4(0.f, 0.f, 0.f, 0.f);
    float4 mx = make_float4(NEG, NEG, NEG, NEG);
    float  cnt = 0.f;
    int    cur = __ldg(&b[start]);

    #define FLUSH()                                                          \
    do {                                                                     \
        const int _base = (rank * NSEG + cur) * H + lane * 4;                \
        atomicAdd(&g_sum [_base + 0], s.x);  atomicAdd(&g_sum [_base + 1], s.y);  \
        atomicAdd(&g_sum [_base + 2], s.z);  atomicAdd(&g_sum [_base + 3], s.w);  \
        atomicAdd(&g_gsum[_base + 0], gs.x); atomicAdd(&g_gsum[_base + 1], gs.y); \
        atomicAdd(&g_gsum[_base + 2], gs.z); atomicAdd(&g_gsum[_base + 3], gs.w); \
        atomicMaxF(&g_max[_base + 0], mx.x); atomicMaxF(&g_max[_base + 1], mx.y); \
        atomicMaxF(&g_max[_base + 2], mx.z); atomicMaxF(&g_max[_base + 3], mx.w); \
        if (lane == 0) atomicAdd(&g_cnt[rank * NSEG + cur], cnt);            \
        s  = make_float4(0.f, 0.f, 0.f, 0.f);                                \
        gs = make_float4(0.f, 0.f, 0.f, 0.f);                                \
        mx = make_float4(NEG, NEG, NEG, NEG);                                \
        cnt = 0.f;                                                           \
    } while (0)

    int row = start;

    for (; row + U <= end; row += U) {
        float4 hv[U];
        float  p[U];
        // vector loads of the 8 segment ids (row is U-aligned)
        const int4 bv0 = *reinterpret_cast<const int4*>(b + row);
        const int4 bv1 = *reinterpret_cast<const int4*>(b + row + 4);

        #pragma unroll
        for (int i = 0; i < U; ++i)
            hv[i] = reinterpret_cast<const float4*>(h + (size_t)(row + i) * H)[lane];

        #pragma unroll
        for (int i = 0; i < U; ++i)
            p[i] = hv[i].x * wg.x + hv[i].y * wg.y + hv[i].z * wg.z + hv[i].w * wg.w;

        // interleaved butterflies: 8 independent reductions share latency
        #pragma unroll
        for (int off = 16; off; off >>= 1) {
            #pragma unroll
            for (int i = 0; i < U; ++i)
                p[i] += __shfl_xor_sync(0xffffffffu, p[i], off);
        }

        if (bv1.w == cur) {
            // fast path: whole group in current segment (b sorted)
            #pragma unroll
            for (int i = 0; i < U; ++i) {
                const float g = 1.f / (1.f + __expf(-(p[i] + bg)));
                s.x += hv[i].x; s.y += hv[i].y; s.z += hv[i].z; s.w += hv[i].w;
                gs.x = fmaf(g, hv[i].x, gs.x); gs.y = fmaf(g, hv[i].y, gs.y);
                gs.z = fmaf(g, hv[i].z, gs.z); gs.w = fmaf(g, hv[i].w, gs.w);
                mx.x = fmaxf(mx.x, hv[i].x);  mx.y = fmaxf(mx.y, hv[i].y);
                mx.z = fmaxf(mx.z, hv[i].z);  mx.w = fmaxf(mx.w, hv[i].w);
            }
            cnt += (float)U;
        } else {
            // slow path: at least one boundary inside the group
            int sg[U];
            sg[0] = bv0.x; sg[1] = bv0.y; sg[2] = bv0.z; sg[3] = bv0.w;
            sg[4] = bv1.x; sg[5] = bv1.y; sg[6] = bv1.z; sg[7] = bv1.w;
            #pragma unroll
            for (int i = 0; i < U; ++i) {
                if (sg[i] != cur) { FLUSH(); cur = sg[i]; }
                const float g = 1.f / (1.f + __expf(-(p[i] + bg)));
                s.x += hv[i].x; s.y += hv[i].y; s.z += hv[i].z; s.w += hv[i].w;
                gs.x = fmaf(g, hv[i].x, gs.x); gs.y = fmaf(g, hv[i].y, gs.y);
                gs.z = fmaf(g, hv[i].z, gs.z); gs.w = fmaf(g, hv[i].w, gs.w);
                mx.x = fmaxf(mx.x, hv[i].x);  mx.y = fmaxf(mx.y, hv[i].y);
                mx.z = fmaxf(mx.z, hv[i].z);  mx.w = fmaxf(mx.w, hv[i].w);
                cnt += 1.f;
            }
        }
    }

    // tail (scalar)
    for (; row < end; ++row) {
        float4 hv = reinterpret_cast<const float4*>(h + (size_t)row * H)[lane];
        int    sg = __ldg(&b[row]);
        if (sg != cur) { FLUSH(); cur = sg; }
        float p = hv.x * wg.x + hv.y * wg.y + hv.z * wg.z + hv.w * wg.w;
        p = warp_sum(p);
        const float g = 1.f / (1.f + __expf(-(p + bg)));
        s.x += hv.x; s.y += hv.y; s.z += hv.z; s.w += hv.w;
        gs.x = fmaf(g, hv.x, gs.x); gs.y = fmaf(g, hv.y, gs.y);
        gs.z = fmaf(g, hv.z, gs.z); gs.w = fmaf(g, hv.w, gs.w);
        mx.x = fmaxf(mx.x, hv.x);  mx.y = fmaxf(mx.y, hv.y);
        mx.z = fmaxf(mx.z, hv.z);  mx.w = fmaxf(mx.w, hv.w);
        cnt += 1.f;
    }

    FLUSH();
    #undef FLUSH
}

// ---------------- 3. projection, split-k by aggregate type (unchanged) ----------------
__global__ __launch_bounds__(256) void proj_kernel(
    const float* __restrict__ Wp0,
    const float* __restrict__ Wp1,
    const float* __restrict__ Wp2)
{
    const int segBase = blockIdx.x * SEGT;
    const int q       = blockIdx.y;          // 0..3
    const int rank    = blockIdx.z;
    const int t       = threadIdx.x;

    const float* Wp = (rank == 0) ? Wp0 : (rank == 1) ? Wp1 : Wp2;

    __shared__ float sa[SEGT][H];

    for (int idx = t; idx < SEGT * H; idx += 256) {
        const int sl  = idx >> 7;
        const int jj  = idx & (H - 1);
        const int seg = segBase + sl;
        const int gb  = (rank * NSEG + seg) * H + jj;
        float val;
        if (q == 0)      val = g_sum[gb];
        else if (q == 1) val = g_sum[gb] / fmaxf(g_cnt[rank * NSEG + seg], 1.f);
        else if (q == 2) { const float mv = g_max[gb];
                           val = (g_cnt[rank * NSEG + seg] > 0.f) ? mv : 0.f; }
        else             val = g_gsum[gb];
        sa[sl][jj] = val;
    }
    __syncthreads();

    const int j   = t & (H - 1);
    const int sub = t >> 7;
    const int s0  = sub * 4;

    const float* wq = Wp + q * H * H + j;
    float a0 = 0.f, a1 = 0.f, a2 = 0.f, a3 = 0.f;
    #pragma unroll 4
    for (int k = 0; k < H; ++k) {
        const float wv = __ldg(&wq[k * H]);
        a0 = fmaf(sa[s0 + 0][k], wv, a0);
        a1 = fmaf(sa[s0 + 1][k], wv, a1);
        a2 = fmaf(sa[s0 + 2][k], wv, a2);
        a3 = fmaf(sa[s0 + 3][k], wv, a3);
    }

    const int gb = (rank * NSEG + segBase + s0) * H + j;
    atomicAdd(&g_r[gb],         a0);
    atomicAdd(&g_r[gb + H],     a1);
    atomicAdd(&g_r[gb + 2 * H], a2);
    atomicAdd(&g_r[gb + 3 * H], a3);
}

// ---------------- 4. head: 512 threads, 4-way k-split ----------------
// All quarters redundantly compute LN (block sums are exactly 4x, divided out).
__global__ __launch_bounds__(512) void head_kernel(
    const float* __restrict__ gamma, const float* __restrict__ beta,
    const float* __restrict__ W1,    const float* __restrict__ b1f,
    const float* __restrict__ W2,    const float* __restrict__ b2f,
    float* __restrict__ out)
{
    const int seg  = blockIdx.x;
    const int t    = threadIdx.x;
    const int j    = t & (H - 1);
    const int qt   = t >> 7;                 // 0..3
    const int warp = t >> 5;                 // 0..15

    __shared__ float sx[3 * H];
    __shared__ float part[512];
    __shared__ float red[16];

    const float v0 = g_r[(0 * NSEG + seg) * H + j];
    const float v1 = g_r[(1 * NSEG + seg) * H + j];
    const float v2 = g_r[(2 * NSEG + seg) * H + j];

    // mean (each element counted 4x across quarters)
    float loc = warp_sum(v0 + v1 + v2);
    if ((t & 31) == 0) red[warp] = loc;
    __syncthreads();
    float tot = 0.f;
    #pragma unroll
    for (int w = 0; w < 16; ++w) tot += red[w];
    const float mu = tot * (1.f / (4.f * 3.f * H));
    __syncthreads();

    // variance (also 4x)
    const float d0 = v0 - mu, d1 = v1 - mu, d2 = v2 - mu;
    float loc2 = warp_sum(d0 * d0 + d1 * d1 + d2 * d2);
    if ((t & 31) == 0) red[warp] = loc2;
    __syncthreads();
    float tot2 = 0.f;
    #pragma unroll
    for (int w = 0; w < 16; ++w) tot2 += red[w];
    const float var  = tot2 * (1.f / (4.f * 3.f * H));
    const float rstd = rsqrtf(var + LN_EPS);
    __syncthreads();

    if (qt == 0) {
        const float xn0 = d0 * rstd * gamma[j]         + beta[j];
        const float xn1 = d1 * rstd * gamma[H + j]     + beta[H + j];
        const float xn2 = d2 * rstd * gamma[2 * H + j] + beta[2 * H + j];
        sx[j]         = silu(xn0);
        sx[H + j]     = silu(xn1);
        sx[2 * H + j] = silu(xn2);
    }
    __syncthreads();

    // x @ W1: quarter qt sums k in [qt*96, qt*96+96), 4 accumulators
    const int k0 = qt * 96;
    float a0 = 0.f, a1 = 0.f, a2 = 0.f, a3 = 0.f;
    #pragma unroll 4
    for (int k = 0; k < 96; k += 4) {
        a0 = fmaf(sx[k0 + k + 0], W1[(k0 + k + 0) * H + j], a0);
        a1 = fmaf(sx[k0 + k + 1], W1[(k0 + k + 1) * H + j], a1);
        a2 = fmaf(sx[k0 + k + 2], W1[(k0 + k + 2) * H + j], a2);
        a3 = fmaf(sx[k0 + k + 3], W1[(k0 + k + 3) * H + j], a3);
    }
    part[t] = (a0 + a1) + (a2 + a3);
    __syncthreads();

    // combine quarters -> SiLU -> dot with W2 (quarter 0 only)
    float o = 0.f;
    if (qt == 0) {
        const float acc = part[j] + part[128 + j] + part[256 + j] + part[384 + j] + b1f[j];
        o = silu(acc) * W2[j];
    }
    o = warp_sum(o);
    if ((t & 31) == 0) red[warp] = o;
    __syncthreads();
    if (t == 0)
        out[seg] = red[0] + red[1] + red[2] + red[3] + b2f[0];
}

// ---------------- launcher ----------------
extern "C" void kernel_launch(void* const* d_in, const int* in_sizes, int n_in,
                              void* d_out, int out_size)
{
    const float* h0  = (const float*)d_in[0];
    const float* h1  = (const float*)d_in[1];
    const float* h2  = (const float*)d_in[2];
    const int*   b0  = (const int*)  d_in[3];
    const int*   b1  = (const int*)  d_in[4];
    const int*   b2  = (const int*)  d_in[5];
    const float* Wg0 = (const float*)d_in[6];
    const float* bg0 = (const float*)d_in[7];
    const float* Wg1 = (const float*)d_in[8];
    const float* bg1 = (const float*)d_in[9];
    const float* Wg2 = (const float*)d_in[10];
    const float* bg2 = (const float*)d_in[11];
    const float* Wp0 = (const float*)d_in[12];
    const float* bp0 = (const float*)d_in[13];
    const float* Wp1 = (const float*)d_in[14];
    const float* bp1 = (const float*)d_in[15];
    const float* Wp2 = (const float*)d_in[16];
    const float* bp2 = (const float*)d_in[17];
    const float* gamma = (const float*)d_in[18];
    const float* beta  = (const float*)d_in[19];
    const float* W1    = (const float*)d_in[20];
    const float* b1f   = (const float*)d_in[21];
    const float* W2    = (const float*)d_in[22];
    const float* b2f   = (const float*)d_in[23];

    const int N0 = in_sizes[3];
    const int N1 = in_sizes[4];
    const int N2 = in_sizes[5];

    // 1. zero segment accumulators; seed g_r with bp
    zero_kernel<<<(RANKS * NSEG * H + 255) / 256, 256>>>(bp0, bp1, bp2);

    // 2. single balanced wave over all node features (blocks proportional to N)
    const long long Nt = (long long)N0 + N1 + N2;
    int g0 = (int)((AGG_BLOCKS * (long long)N0 + Nt / 2) / Nt);
    int g1 = (int)((AGG_BLOCKS * (long long)N1 + Nt / 2) / Nt);
    if (g0 < 1) g0 = 1;
    if (g1 < 1) g1 = 1;
    if (g0 + g1 > AGG_BLOCKS - 1) g1 = AGG_BLOCKS - 1 - g0;
    agg_kernel<<<AGG_BLOCKS, 256>>>(h0, h1, h2, b0, b1, b2,
                                    Wg0, Wg1, Wg2, bg0, bg1, bg2,
                                    N0, N1, N2, g0, g1);

    // 3. projection: split-k by aggregate type, atomic accumulation
    dim3 gProj(NSEG / SEGT, 4, RANKS);
    proj_kernel<<<gProj, 256>>>(Wp0, Wp1, Wp2);

    // 4. head (512 threads, 4-way k-split)
    head_kernel<<<NSEG, 512>>>(gamma, beta, W1, b1f, W2, b2f, (float*)d_out);
}